// round 15
// baseline (speedup 1.0000x reference)
#include <cuda_runtime.h>
#include <stdint.h>

#define B 16
#define N 4096
#define F 128
#define K 1024
#define ROWS_PER_CTA 8
#define ADJ_BLOCKS ((B * K) / ROWS_PER_CTA)   // 2048
#define HB 11
#define NB (1 << HB)   // 2048 histogram buckets

typedef unsigned long long u64;
typedef unsigned int u32;

// scratch (no allocations allowed; statics zero-initialized)
__device__ float g_scores[B * N];
__device__ int   g_done[B];              // last-block-done counters
__device__ int   g_topk_idx[B * K];
__device__ float g_topk_val[B * K];
__device__ u64   g_sortbuf[B * 4096];    // fallback-only scratch (never hot)

__device__ __forceinline__ unsigned map_f32(float f) {
    unsigned u = __float_as_uint(f);
    return (u & 0x80000000u) ? ~u : (u | 0x80000000u);
}

__device__ __forceinline__ void reg_stages32(u32& e0, u32& e1, int i0, int i1,
                                             int lane, int kk) {
    if (kk >= 64) {
        bool desc = ((i0 & kk) == 0);
        if (desc ? (e0 < e1) : (e0 > e1)) { u32 t = e0; e0 = e1; e1 = t; }
    }
#pragma unroll
    for (int j = 16; j >= 1; j >>= 1) {
        if (j <= (kk >> 1)) {
            bool d0 = ((i0 & kk) == 0);
            bool d1 = ((i1 & kk) == 0);
            bool up = (lane & j) != 0;
            u32 p0 = __shfl_xor_sync(0xffffffffu, e0, j);
            u32 p1 = __shfl_xor_sync(0xffffffffu, e1, j);
            e0 = (d0 ^ up) ? max(e0, p0) : min(e0, p0);
            e1 = (d1 ^ up) ? max(e1, p1) : min(e1, p1);
        }
    }
}

// ---------------------------------------------------------------------------
// Kernel 1 (merged): scores for 32 rows/CTA; last-done CTA per batch runs
// that batch's top-k in-launch. Executor holds NO per-key registers: scores
// are re-read via __ldcg (L2-hot 16KB) per sub-phase; ties resolved by
// position. smem ~25KB, regs capped -> scores phase keeps its occupancy.
// ---------------------------------------------------------------------------
__global__ void __launch_bounds__(256, 6) scores_topk_kernel(
        const float* __restrict__ ne, const float* __restrict__ w) {
    __shared__ u32 cand[2048];       // 8 KB sorted candidate keys
    __shared__ int tiebuf[2048];     // 8 KB tie registration
    __shared__ int hist[NB];         // 8 KB histogram -> tie counters
    __shared__ int seg[256];         // 1 KB
    __shared__ int s_t0, s_cnt, s_exec;

    const int tid  = threadIdx.x;
    const int lane = tid & 31;
    const int warp = tid >> 5;
    const int b    = blockIdx.x >> 7;            // 128 CTAs per batch

    // ===================== phase 1: scores (R13 logic) =====================
    {
        int row0 = (blockIdx.x * 8 + warp) * 4;
        const float4* wv = reinterpret_cast<const float4*>(w);
        float4 b4 = wv[lane];
        const float4* r0 = reinterpret_cast<const float4*>(ne + (size_t)row0 * F);
        const float4* r1 = reinterpret_cast<const float4*>(ne + (size_t)(row0 + 1) * F);
        const float4* r2 = reinterpret_cast<const float4*>(ne + (size_t)(row0 + 2) * F);
        const float4* r3 = reinterpret_cast<const float4*>(ne + (size_t)(row0 + 3) * F);
        float4 a0 = r0[lane], a1 = r1[lane], a2 = r2[lane], a3 = r3[lane];

        float s0 = a0.x * b4.x + a0.y * b4.y + a0.z * b4.z + a0.w * b4.w;
        float s1 = a1.x * b4.x + a1.y * b4.y + a1.z * b4.z + a1.w * b4.w;
        float s2 = a2.x * b4.x + a2.y * b4.y + a2.z * b4.z + a2.w * b4.w;
        float s3 = a3.x * b4.x + a3.y * b4.y + a3.z * b4.z + a3.w * b4.w;
#pragma unroll
        for (int off = 16; off; off >>= 1) {
            s0 += __shfl_xor_sync(0xffffffffu, s0, off);
            s1 += __shfl_xor_sync(0xffffffffu, s1, off);
            s2 += __shfl_xor_sync(0xffffffffu, s2, off);
            s3 += __shfl_xor_sync(0xffffffffu, s3, off);
        }
        if (lane == 0) {
            *reinterpret_cast<float4*>(g_scores + row0) =
                make_float4(s0, s1, s2, s3);
            __threadfence();
        }
    }
    __syncthreads();

    // ================== last-block-done election per batch ==================
    if (tid == 0) {
        int prev = atomicAdd(&g_done[b], 1);
        s_exec = (prev == 127);
        if (prev == 127) g_done[b] = 0;          // reset for graph replay
    }
    __syncthreads();
    if (!s_exec) return;
    __threadfence();                             // acquire peers' scores

    // ===================== phase 2: top-k (256 threads) ====================
    const float* sc = g_scores + b * N;

    for (int k2 = 0; k2 < 8; k2++) hist[tid + k2 * 256] = 0;
    __syncthreads();

    // pass A: histogram (no key registers kept)
    for (int q = 0; q < 16; q++) {
        unsigned m = map_f32(__ldcg(&sc[tid + q * 256]));
        atomicAdd(&hist[m >> (32 - HB)], 1);
    }
    __syncthreads();

    // ---- cutoff bucket t0 ----
    {
        int ssum = 0;
#pragma unroll
        for (int k2 = 0; k2 < 8; k2++) ssum += hist[8 * tid + k2];
        seg[tid] = ssum;
    }
    __syncthreads();
    if (warp == 0) {
        int v = 0;
#pragma unroll
        for (int k2 = 0; k2 < 8; k2++) v += seg[8 * lane + k2];
        int s = v;
#pragma unroll
        for (int off = 1; off < 32; off <<= 1) {
            int t = __shfl_down_sync(0xffffffffu, s, off);
            if (lane + off < 32) s += t;
        }
        unsigned mm = __ballot_sync(0xffffffffu, s >= K);
        int wstar = 31 - __clz(mm);
        int sW = __shfl_sync(0xffffffffu, s, wstar);
        int vW = __shfl_sync(0xffffffffu, v, wstar);
        int run = sW - vW;
        int segbase = wstar * 64;
        int t0 = 0;
#pragma unroll
        for (int c = 1; c >= 0; c--) {
            int bkt = segbase + c * 32 + lane;
            int hv = hist[bkt];
            int s2 = hv;
#pragma unroll
            for (int off = 1; off < 32; off <<= 1) {
                int t = __shfl_down_sync(0xffffffffu, s2, off);
                if (lane + off < 32) s2 += t;
            }
            unsigned m2 = __ballot_sync(0xffffffffu, run + s2 >= K);
            if (m2) { t0 = segbase + c * 32 + (31 - __clz(m2)); break; }
            run += __shfl_sync(0xffffffffu, s2, 0);
        }
        if (lane == 0) { s_t0 = t0; s_cnt = 0; }
    }
    __syncthreads();

    // pass B: compact candidate keys (re-read scores; L2-hot)
    const int t0 = s_t0;
    for (int q = 0; q < 16; q++) {
        unsigned m = map_f32(__ldcg(&sc[tid + q * 256]));
        bool p = (int)(m >> (32 - HB)) >= t0;
        unsigned mask = __ballot_sync(0xffffffffu, p);
        int cnt = __popc(mask);
        int base = 0;
        if (lane == 0 && cnt) base = atomicAdd(&s_cnt, cnt);
        base = __shfl_sync(0xffffffffu, base, 0);
        if (p) cand[base + __popc(mask & ((1u << lane) - 1u))] = m;
    }
    __syncthreads();
    const int M = s_cnt;

    if (M <= 2048) {
        for (int i = M + tid; i < 2048; i += 256) cand[i] = 0;
        __syncthreads();

        // register stages kk=2..64 (8 warps x 4 tiles of 64)
#pragma unroll
        for (int t = 0; t < 4; t++) {
            int base = (warp + t * 8) * 64;
            int i0 = base + lane, i1 = base + 32 + lane;
            u32 e0 = cand[i0], e1 = cand[i1];
#pragma unroll
            for (int kk = 2; kk <= 64; kk <<= 1)
                reg_stages32(e0, e1, i0, i1, lane, kk);
            cand[i0] = e0; cand[i1] = e1;
        }
        __syncthreads();

#pragma unroll
        for (int kk = 128; kk <= 2048; kk <<= 1) {
            for (int j = kk >> 1; j >= 64; j >>= 1) {
#pragma unroll
                for (int p = 0; p < 4; p++) {
                    int q = tid + p * 256;
                    int i = 2 * q - (q & (j - 1));
                    int x = i + j;
                    bool desc = ((i & kk) == 0);
                    u32 a = cand[i], c = cand[x];
                    if (desc ? (a < c) : (a > c)) { cand[i] = c; cand[x] = a; }
                }
                __syncthreads();
            }
#pragma unroll
            for (int t = 0; t < 4; t++) {
                int base = (warp + t * 8) * 64;
                int i0 = base + lane, i1 = base + 32 + lane;
                u32 e0 = cand[i0], e1 = cand[i1];
                reg_stages32(e0, e1, i0, i1, lane, kk);
                cand[i0] = e0; cand[i1] = e1;
            }
            __syncthreads();
        }

        // re-zero hist as tie counters
        for (int k2 = 0; k2 < 8; k2++) hist[tid + k2 * 256] = 0;
        __syncthreads();

        // pass C: registration (re-read scores; no per-key registers)
        for (int q = 0; q < 16; q++) {
            unsigned m = map_f32(__ldcg(&sc[tid + q * 256]));
            if ((int)(m >> (32 - HB)) >= t0) {
                int lo = 0, hi = 2047;           // descending, m present
                while (lo < hi) {
                    int mid = (lo + hi) >> 1;
                    if (cand[mid] > m) lo = mid + 1; else hi = mid;
                }
                int a = atomicAdd(&hist[lo], 1);
                tiebuf[lo + a] = tid + q * 256;
            }
        }
        __syncthreads();

        // pass D: resolution by position. First-occurrence positions own
        // their tie run; emit ranks p..p+d-1 in ascending-index order.
        for (int q = 0; q < 8; q++) {
            int p = tid + q * 256;
            if (p < M && p < K + 1024) {         // ranks >= K+run never matter
                int d = hist[p];
                if (d > 0) {                     // p is a first occurrence
                    u32 m = cand[p];
                    unsigned uu = (m & 0x80000000u) ? (m ^ 0x80000000u) : ~m;
                    float val = __uint_as_float(uu);
                    if (d == 1) {
                        if (p < K) {
                            g_topk_idx[b * K + p] = tiebuf[p];
                            g_topk_val[b * K + p] = val;
                        }
                    } else {
                        int prev = -1;
                        for (int j = 0; j < d && p + j < K; j++) {
                            int mn = 0x7fffffff;
                            for (int t = 0; t < d; t++) {
                                int v = tiebuf[p + t];
                                if (v > prev && v < mn) mn = v;
                            }
                            g_topk_idx[b * K + p + j] = mn;
                            g_topk_val[b * K + p + j] = val;
                            prev = mn;
                        }
                    }
                }
            }
        }
    } else {
        // ===== fallback (unreachable for this data): u64 sort in global =====
        u64* sb = g_sortbuf + b * 4096;
        for (int q = 0; q < 16; q++) {
            int i = tid + q * 256;
            u64 kk = (((u64)map_f32(__ldcg(&sc[i]))) << 12) |
                     (unsigned)(N - 1 - i);
            sb[i] = kk;
        }
        __syncthreads();
        for (int kk = 2; kk <= 4096; kk <<= 1) {
            for (int j = kk >> 1; j > 0; j >>= 1) {
                for (int q = tid; q < 2048; q += 256) {
                    int i = 2 * q - (q & (j - 1));
                    int x = i + j;
                    bool desc = ((i & kk) == 0);
                    u64 a = sb[i], c = sb[x];
                    if (desc ? (a < c) : (a > c)) { sb[i] = c; sb[x] = a; }
                }
                __syncthreads();
            }
        }
        for (int q = 0; q < 4; q++) {
            int r = tid + q * 256;
            u64 key = sb[r];
            int idx = (N - 1) - (int)(key & 0xFFFu);
            unsigned m = (unsigned)(key >> 12);
            unsigned uu = (m & 0x80000000u) ? (m ^ 0x80000000u) : ~m;
            g_topk_idx[b * K + r] = idx;
            g_topk_val[b * K + r] = __uint_as_float(uu);
        }
    }
}

// ---------------------------------------------------------------------------
// cp.async helpers
// ---------------------------------------------------------------------------
__device__ __forceinline__ void cp16(u32 smem_addr, const void* gmem) {
    asm volatile("cp.async.cg.shared.global [%0], [%1], 16;"
                 :: "r"(smem_addr), "l"(gmem));
}
__device__ __forceinline__ void cp_commit() {
    asm volatile("cp.async.commit_group;" ::: "memory");
}
__device__ __forceinline__ void cp_wait0() {
    asm volatile("cp.async.wait_group 0;" ::: "memory");
}

// ---------------------------------------------------------------------------
// Kernel 2 (fused, byte-identical to R13): full-row streaming adj gather +
// pooled_nodes.
// ---------------------------------------------------------------------------
__global__ void __launch_bounds__(256) fused_kernel(const float* __restrict__ ne,
                                                    const float* __restrict__ adj,
                                                    float* __restrict__ out) {
    if (blockIdx.x < ADJ_BLOCKS) {
        __shared__ __align__(16) float rowbuf[2][N];   // 32 KB
        __shared__ __align__(16) int   cidx[K];        //  4 KB (topk order)
        __shared__ int ridx[ROWS_PER_CTA];

        float* aout = out + (size_t)B * K * F;
        const int b     = blockIdx.x >> 7;             // 128 CTAs per batch
        const int rbase = (blockIdx.x & 127) * ROWS_PER_CTA;
        const int tid   = threadIdx.x;

#pragma unroll
        for (int q = 0; q < 4; q++)
            cidx[tid + q * 256] = g_topk_idx[b * K + tid + q * 256];
        if (tid < ROWS_PER_CTA) ridx[tid] = g_topk_idx[b * K + rbase + tid];
        __syncthreads();

        int4 cc = *reinterpret_cast<int4*>(&cidx[4 * tid]);

        {
            const char* g = (const char*)(adj + ((size_t)b * N + ridx[0]) * N);
            u32 s = (u32)__cvta_generic_to_shared(rowbuf[0]);
#pragma unroll
            for (int k2 = 0; k2 < 4; k2++)
                cp16(s + (tid + k2 * 256) * 16, g + (tid + k2 * 256) * 16);
            cp_commit();
        }

#pragma unroll
        for (int rr = 0; rr < ROWS_PER_CTA; rr++) {
            cp_wait0();
            __syncthreads();
            if (rr + 1 < ROWS_PER_CTA) {
                const char* g = (const char*)(adj +
                                ((size_t)b * N + ridx[rr + 1]) * N);
                u32 s = (u32)__cvta_generic_to_shared(rowbuf[(rr + 1) & 1]);
#pragma unroll
                for (int k2 = 0; k2 < 4; k2++)
                    cp16(s + (tid + k2 * 256) * 16, g + (tid + k2 * 256) * 16);
                cp_commit();
            }
            const float* rb = rowbuf[rr & 1];
            float4 v = make_float4(rb[cc.x], rb[cc.y], rb[cc.z], rb[cc.w]);
            float* orow = aout + ((size_t)b * K + rbase + rr) * K;
            *reinterpret_cast<float4*>(orow + 4 * tid) = v;
        }
    } else {
        int blk  = blockIdx.x - ADJ_BLOCKS;              // [0, 2048)
        int warp = (blk * 256 + (int)threadIdx.x) >> 5;  // [0, B*K)
        int lane = threadIdx.x & 31;
        int b    = warp >> 10;
        int idx  = g_topk_idx[warp];
        float g  = tanhf(g_topk_val[warp]);
        const float4* src = reinterpret_cast<const float4*>(
            ne + ((size_t)b * N + idx) * F);
        float4* dst = reinterpret_cast<float4*>(out + (size_t)warp * F);
        float4 v = src[lane];
        v.x *= g; v.y *= g; v.z *= g; v.w *= g;
        dst[lane] = v;
    }
}

// ---------------------------------------------------------------------------
extern "C" void kernel_launch(void* const* d_in, const int* in_sizes, int n_in,
                              void* d_out, int out_size) {
    const float* ne  = (const float*)d_in[0];  // [B,N,F]
    const float* adj = (const float*)d_in[1];  // [B,N,N]
    const float* w   = (const float*)d_in[2];  // [F]
    float* out       = (float*)d_out;

    scores_topk_kernel<<<(B * N) / 32, 256>>>(ne, w);
    fused_kernel<<<ADJ_BLOCKS + (B * K) / 8, 256>>>(ne, adj, out);
}

// round 16
// speedup vs baseline: 1.5447x; 1.5447x over previous
#include <cuda_runtime.h>
#include <stdint.h>

#define B 16
#define N 4096
#define F 128
#define K 1024
#define ROWS_PER_CTA 8
#define ADJ_BLOCKS ((B * K) / ROWS_PER_CTA)   // 2048
#define HB 11
#define NB (1 << HB)   // 2048 histogram buckets

typedef unsigned long long u64;
typedef unsigned int u32;

// scratch (no allocations allowed)
__device__ float g_scores[B * N];
__device__ int   g_topk_idx[B * K];
__device__ float g_topk_val[B * K];

__device__ __forceinline__ unsigned map_f32(float f) {
    unsigned u = __float_as_uint(f);
    return (u & 0x80000000u) ? ~u : (u | 0x80000000u);
}

// ---------------------------------------------------------------------------
// Kernel 1: scores. 4 rows per warp (R7/R13 config, measured 9.3-9.6us).
// ---------------------------------------------------------------------------
__global__ void scores_kernel(const float* __restrict__ ne,
                              const float* __restrict__ w) {
    int warp = (blockIdx.x * blockDim.x + threadIdx.x) >> 5;  // [0, B*N/4)
    int lane = threadIdx.x & 31;
    int row0 = warp * 4;
    if (row0 >= B * N) return;

    const float4* wv = reinterpret_cast<const float4*>(w);
    float4 b4 = wv[lane];
    const float4* r0 = reinterpret_cast<const float4*>(ne + (size_t)row0 * F);
    const float4* r1 = reinterpret_cast<const float4*>(ne + (size_t)(row0 + 1) * F);
    const float4* r2 = reinterpret_cast<const float4*>(ne + (size_t)(row0 + 2) * F);
    const float4* r3 = reinterpret_cast<const float4*>(ne + (size_t)(row0 + 3) * F);
    float4 a0 = r0[lane], a1 = r1[lane], a2 = r2[lane], a3 = r3[lane];

    float s0 = a0.x * b4.x + a0.y * b4.y + a0.z * b4.z + a0.w * b4.w;
    float s1 = a1.x * b4.x + a1.y * b4.y + a1.z * b4.z + a1.w * b4.w;
    float s2 = a2.x * b4.x + a2.y * b4.y + a2.z * b4.z + a2.w * b4.w;
    float s3 = a3.x * b4.x + a3.y * b4.y + a3.z * b4.z + a3.w * b4.w;
#pragma unroll
    for (int off = 16; off; off >>= 1) {
        s0 += __shfl_xor_sync(0xffffffffu, s0, off);
        s1 += __shfl_xor_sync(0xffffffffu, s1, off);
        s2 += __shfl_xor_sync(0xffffffffu, s2, off);
        s3 += __shfl_xor_sync(0xffffffffu, s3, off);
    }
    if (lane == 0)
        *reinterpret_cast<float4*>(g_scores + row0) = make_float4(s0, s1, s2, s3);
}

// ---------------------------------------------------------------------------
// Kernel 2: radix-select + 32-bit hybrid bitonic sort + tie-exact ranking.
// (R12/R13 logic, passing at rel_err 7.5e-8.)
// ---------------------------------------------------------------------------
__device__ __forceinline__ void reg_stages32(u32& e0, u32& e1, int i0, int i1,
                                             int lane, int kk) {
    if (kk >= 64) {
        bool desc = ((i0 & kk) == 0);
        if (desc ? (e0 < e1) : (e0 > e1)) { u32 t = e0; e0 = e1; e1 = t; }
    }
#pragma unroll
    for (int j = 16; j >= 1; j >>= 1) {
        if (j <= (kk >> 1)) {
            bool d0 = ((i0 & kk) == 0);
            bool d1 = ((i1 & kk) == 0);
            bool up = (lane & j) != 0;
            u32 p0 = __shfl_xor_sync(0xffffffffu, e0, j);
            u32 p1 = __shfl_xor_sync(0xffffffffu, e1, j);
            e0 = (d0 ^ up) ? max(e0, p0) : min(e0, p0);
            e1 = (d1 ^ up) ? max(e1, p1) : min(e1, p1);
        }
    }
}

__global__ void __launch_bounds__(1024) topk_kernel() {
    __shared__ u64 candw[4096];      // 32 KB: u32 keys + tiebuf
    __shared__ int hist[NB];         //  8 KB
    __shared__ int wsum[32];
    __shared__ int s_t0, s_cnt;

    u32* cand   = (u32*)candw;
    int* tiebuf = (int*)candw + 4096;

    const int b    = blockIdx.x;
    const int tid  = threadIdx.x;
    const int lane = tid & 31;
    const int warp = tid >> 5;
    const float* sc = g_scores + b * N;

    hist[tid] = 0;
    hist[tid + 1024] = 0;
    __syncthreads();

    u32 mreg[4];
#pragma unroll
    for (int q = 0; q < 4; q++) {
        int i = tid + q * 1024;
        mreg[q] = map_f32(sc[i]);
        atomicAdd(&hist[mreg[q] >> (32 - HB)], 1);
    }
    __syncthreads();

    // ---- cutoff bucket t0 = max t such that count(bucket >= t) >= K ----
    {
        int p = hist[2 * tid] + hist[2 * tid + 1];
        int ws = p;
#pragma unroll
        for (int off = 16; off; off >>= 1)
            ws += __shfl_xor_sync(0xffffffffu, ws, off);
        if (lane == 0) wsum[warp] = ws;
    }
    __syncthreads();
    if (warp == 0) {
        int v = wsum[lane];
        int s = v;
#pragma unroll
        for (int off = 1; off < 32; off <<= 1) {
            int t = __shfl_down_sync(0xffffffffu, s, off);
            if (lane + off < 32) s += t;
        }
        unsigned mm = __ballot_sync(0xffffffffu, s >= K);
        int wstar = 31 - __clz(mm);
        int sW = __shfl_sync(0xffffffffu, s, wstar);
        int vW = __shfl_sync(0xffffffffu, v, wstar);
        int run = sW - vW;
        int segbase = wstar * 64;
        int t0 = 0;
#pragma unroll
        for (int c = 1; c >= 0; c--) {
            int bkt = segbase + c * 32 + lane;
            int hv = hist[bkt];
            int s2 = hv;
#pragma unroll
            for (int off = 1; off < 32; off <<= 1) {
                int t = __shfl_down_sync(0xffffffffu, s2, off);
                if (lane + off < 32) s2 += t;
            }
            unsigned m2 = __ballot_sync(0xffffffffu, run + s2 >= K);
            if (m2) { t0 = segbase + c * 32 + (31 - __clz(m2)); break; }
            run += __shfl_sync(0xffffffffu, s2, 0);
        }
        if (lane == 0) { s_t0 = t0; s_cnt = 0; }
    }
    __syncthreads();

    // ---- compact candidate keys (bucket >= t0), warp-aggregated ----
    const int t0 = s_t0;
#pragma unroll
    for (int q = 0; q < 4; q++) {
        bool p = (int)(mreg[q] >> (32 - HB)) >= t0;
        unsigned mask = __ballot_sync(0xffffffffu, p);
        int cnt = __popc(mask);
        int base = 0;
        if (lane == 0 && cnt) base = atomicAdd(&s_cnt, cnt);
        base = __shfl_sync(0xffffffffu, base, 0);
        if (p) cand[base + __popc(mask & ((1u << lane) - 1u))] = mreg[q];
    }
    __syncthreads();
    const int M = s_cnt;

    if (M <= 2048) {
        // ===== common path: 32-bit sort of 2048, tie-exact rank =====
        for (int i = M + tid; i < 2048; i += 1024) cand[i] = 0;  // real keys > 0
        __syncthreads();

        const int base = warp * 64;
        const int i0 = base + lane, i1 = base + 32 + lane;
        u32 e0, e1;

        e0 = cand[i0]; e1 = cand[i1];
#pragma unroll
        for (int kk = 2; kk <= 64; kk <<= 1)
            reg_stages32(e0, e1, i0, i1, lane, kk);
        cand[i0] = e0; cand[i1] = e1;
        __syncthreads();

#pragma unroll
        for (int kk = 128; kk <= 2048; kk <<= 1) {
            for (int j = kk >> 1; j >= 64; j >>= 1) {
                int i = 2 * tid - (tid & (j - 1));
                int x = i + j;
                bool desc = ((i & kk) == 0);
                u32 a = cand[i], c = cand[x];
                if (desc ? (a < c) : (a > c)) { cand[i] = c; cand[x] = a; }
                __syncthreads();
            }
            e0 = cand[i0]; e1 = cand[i1];
            reg_stages32(e0, e1, i0, i1, lane, kk);
            cand[i0] = e0; cand[i1] = e1;
            __syncthreads();
        }

        // re-zero hist as tie counters
        hist[tid] = 0;
        hist[tid + 1024] = 0;
        __syncthreads();

        // registration: each candidate finds first occurrence lo, registers idx
        int loq[4];
#pragma unroll
        for (int q = 0; q < 4; q++) {
            loq[q] = -1;
            if ((int)(mreg[q] >> (32 - HB)) >= t0) {
                u32 m = mreg[q];
                int lo = 0, hi = 2047;       // descending array, m present
                while (lo < hi) {
                    int mid = (lo + hi) >> 1;
                    if (cand[mid] > m) lo = mid + 1; else hi = mid;
                }
                loq[q] = lo;
                int a = atomicAdd(&hist[lo], 1);
                tiebuf[lo + a] = tid + q * 1024;
            }
        }
        __syncthreads();

        // resolve ranks (tie order: ascending original index) and emit
#pragma unroll
        for (int q = 0; q < 4; q++) {
            if (loq[q] >= 0) {
                int lo = loq[q];
                int idx = tid + q * 1024;
                int d = hist[lo];
                int off = 0;
                if (d > 1)
                    for (int j = 0; j < d; j++)
                        off += (tiebuf[lo + j] < idx);
                int rank = lo + off;
                if (rank < K) {
                    u32 m = mreg[q];
                    unsigned u = (m & 0x80000000u) ? (m ^ 0x80000000u) : ~m;
                    g_topk_idx[b * K + rank] = idx;
                    g_topk_val[b * K + rank] = __uint_as_float(u);
                }
            }
        }
    } else {
        // ===== fallback: full u64 sort (keys unique by idx suffix) =====
#pragma unroll
        for (int q = 0; q < 4; q++) {
            int i = tid + q * 1024;
            candw[i] = (((u64)mreg[q]) << 12) | (unsigned)(N - 1 - i);
        }
        __syncthreads();
        for (int kk = 2; kk <= 4096; kk <<= 1) {
            for (int j = kk >> 1; j > 0; j >>= 1) {
                for (int q = tid; q < 2048; q += 1024) {
                    int i = 2 * q - (q & (j - 1));
                    int x = i + j;
                    bool desc = ((i & kk) == 0);
                    u64 a = candw[i], c = candw[x];
                    if (desc ? (a < c) : (a > c)) { candw[i] = c; candw[x] = a; }
                }
                __syncthreads();
            }
        }
        u64 key = candw[tid];          // rank tid < K
        int idx = (N - 1) - (int)(key & 0xFFFu);
        unsigned m = (unsigned)(key >> 12);
        unsigned u = (m & 0x80000000u) ? (m ^ 0x80000000u) : ~m;
        g_topk_idx[b * K + tid] = idx;
        g_topk_val[b * K + tid] = __uint_as_float(u);
    }
}

// ---------------------------------------------------------------------------
// cp.async helpers
// ---------------------------------------------------------------------------
__device__ __forceinline__ void cp16(u32 smem_addr, const void* gmem) {
    asm volatile("cp.async.cg.shared.global [%0], [%1], 16;"
                 :: "r"(smem_addr), "l"(gmem));
}
__device__ __forceinline__ void cp_commit() {
    asm volatile("cp.async.commit_group;" ::: "memory");
}
__device__ __forceinline__ void cp_wait0() {
    asm volatile("cp.async.wait_group 0;" ::: "memory");
}

// ---------------------------------------------------------------------------
// Kernel 3 (fused): full-row streaming adj gather + pooled_nodes.
// R13 logic with ONE change: per-thread column indices come from a single
// coalesced int4 global load (L2-hot) instead of a 4KB smem cidx array.
// smem drops 37 -> ~32KB => 6 -> 7 CTAs/SM => more cp.async groups in flight.
// ---------------------------------------------------------------------------
__global__ void __launch_bounds__(256) fused_kernel(const float* __restrict__ ne,
                                                    const float* __restrict__ adj,
                                                    float* __restrict__ out) {
    if (blockIdx.x < ADJ_BLOCKS) {
        __shared__ __align__(16) float rowbuf[2][N];   // 32 KB
        __shared__ int ridx[ROWS_PER_CTA];

        float* aout = out + (size_t)B * K * F;
        const int b     = blockIdx.x >> 7;             // 128 CTAs per batch
        const int rbase = (blockIdx.x & 127) * ROWS_PER_CTA;
        const int tid   = threadIdx.x;

        // per-thread output columns: one coalesced int4 load, kept in regs
        int4 cc = *reinterpret_cast<const int4*>(&g_topk_idx[b * K + 4 * tid]);
        if (tid < ROWS_PER_CTA) ridx[tid] = g_topk_idx[b * K + rbase + tid];
        __syncthreads();

        // preload row 0: 4 x 16B chunks per thread, coalesced
        {
            const char* g = (const char*)(adj + ((size_t)b * N + ridx[0]) * N);
            u32 s = (u32)__cvta_generic_to_shared(rowbuf[0]);
#pragma unroll
            for (int k2 = 0; k2 < 4; k2++)
                cp16(s + (tid + k2 * 256) * 16, g + (tid + k2 * 256) * 16);
            cp_commit();
        }

#pragma unroll
        for (int rr = 0; rr < ROWS_PER_CTA; rr++) {
            cp_wait0();
            __syncthreads();            // row rr visible to all threads
            if (rr + 1 < ROWS_PER_CTA) {
                const char* g = (const char*)(adj +
                                ((size_t)b * N + ridx[rr + 1]) * N);
                u32 s = (u32)__cvta_generic_to_shared(rowbuf[(rr + 1) & 1]);
#pragma unroll
                for (int k2 = 0; k2 < 4; k2++)
                    cp16(s + (tid + k2 * 256) * 16, g + (tid + k2 * 256) * 16);
                cp_commit();
            }
            const float* rb = rowbuf[rr & 1];
            float4 v = make_float4(rb[cc.x], rb[cc.y], rb[cc.z], rb[cc.w]);
            float* orow = aout + ((size_t)b * K + rbase + rr) * K;
            *reinterpret_cast<float4*>(orow + 4 * tid) = v;
        }
    } else {
        int blk  = blockIdx.x - ADJ_BLOCKS;              // [0, 2048)
        int warp = (blk * 256 + (int)threadIdx.x) >> 5;  // [0, B*K)
        int lane = threadIdx.x & 31;
        int b    = warp >> 10;
        int idx  = g_topk_idx[warp];
        float g  = tanhf(g_topk_val[warp]);
        const float4* src = reinterpret_cast<const float4*>(
            ne + ((size_t)b * N + idx) * F);
        float4* dst = reinterpret_cast<float4*>(out + (size_t)warp * F);
        float4 v = src[lane];
        v.x *= g; v.y *= g; v.z *= g; v.w *= g;
        dst[lane] = v;
    }
}

// ---------------------------------------------------------------------------
extern "C" void kernel_launch(void* const* d_in, const int* in_sizes, int n_in,
                              void* d_out, int out_size) {
    const float* ne  = (const float*)d_in[0];  // [B,N,F]
    const float* adj = (const float*)d_in[1];  // [B,N,N]
    const float* w   = (const float*)d_in[2];  // [F]
    float* out       = (float*)d_out;

    scores_kernel<<<(B * N) / 32, 256>>>(ne, w);   // 4 rows per warp
    topk_kernel<<<B, 1024>>>();
    fused_kernel<<<ADJ_BLOCKS + (B * K) / 8, 256>>>(ne, adj, out);
}